// round 15
// baseline (speedup 1.0000x reference)
#include <cuda_runtime.h>
#include <cuda_fp16.h>

#define D_IN  128
#define D_OUT 64
#define MAX_NODES 50000
#define RPB 64    // rows per block (gemm)

// scratch: h = x @ W stored fp16 (6.4 MB), CSR row pointers
__device__ __half g_h[MAX_NODES * D_OUT];
__device__ int    g_row_ptr[MAX_NODES + 1];

// ---------------------------------------------------------------------------
// CSR row offsets via boundary detection, 16 edges per thread (4x int4, MLP=4).
// ---------------------------------------------------------------------------
__global__ void rowptr_kernel(const int* __restrict__ dst,
                              int n_edges, int n_nodes) {
    int t  = blockIdx.x * blockDim.x + threadIdx.x;
    int e0 = t << 4;
    if (e0 >= n_edges) return;

    int d[17];
    d[0] = (e0 == 0) ? -1 : __ldg(dst + e0 - 1);

    if (e0 + 16 <= n_edges) {
        int4 q0 = __ldg((const int4*)(dst + e0));
        int4 q1 = __ldg((const int4*)(dst + e0 + 4));
        int4 q2 = __ldg((const int4*)(dst + e0 + 8));
        int4 q3 = __ldg((const int4*)(dst + e0 + 12));
        d[1]=q0.x; d[2]=q0.y; d[3]=q0.z; d[4]=q0.w;
        d[5]=q1.x; d[6]=q1.y; d[7]=q1.z; d[8]=q1.w;
        d[9]=q2.x; d[10]=q2.y; d[11]=q2.z; d[12]=q2.w;
        d[13]=q3.x; d[14]=q3.y; d[15]=q3.z; d[16]=q3.w;
    } else {
        #pragma unroll
        for (int j = 0; j < 16; j++)
            d[j + 1] = (e0 + j < n_edges) ? __ldg(dst + e0 + j) : d[j];
    }

    #pragma unroll
    for (int j = 0; j < 16; j++) {
        int ee = e0 + j;
        if (ee < n_edges)
            for (int i = d[j] + 1; i <= d[j + 1]; i++) g_row_ptr[i] = ee;
    }
    if (e0 + 16 >= n_edges) {
        int last = d[16];
        for (int i = last + 1; i <= n_nodes; i++) g_row_ptr[i] = n_edges;
    }
}

// ---------------------------------------------------------------------------
// h = x @ W, mma.m16n8k16 fp16, fp32 accum.
// x staged via cp.async (16 B LDGSTS, 8/thread, no register staging ->
// full MLP, DRAM sweep no longer latency-bound).  Xs holds RAW fp32
// (stride 132); fp16 conversion happens at fragment read (compute phase
// is idle anyway).  W staged coalesced float4 -> transposed fp16 STS.16.
// ---------------------------------------------------------------------------
__device__ __forceinline__ unsigned f2h2(float lo, float hi) {
    __half2 h = __floats2half2_rn(lo, hi);
    return *(unsigned*)&h;
}

__global__ void __launch_bounds__(256)
gemm_kernel(const float* __restrict__ x,
            const float* __restrict__ w,
            int n_nodes) {
    __shared__ float  Xs[RPB][132];     // 33.8 KB raw fp32
    __shared__ __half Wt[D_OUT][136];   // 17.4 KB (W transposed: [n][k])

    int tid   = threadIdx.x;
    int lane  = tid & 31;
    int warp  = tid >> 5;
    int row0  = blockIdx.x * RPB;
    int g     = lane >> 2;          // 0..7
    int tig   = lane & 3;           // 0..3
    int wrow  = (warp >> 1) * 16;   // m-tile base row within block
    int nhalf = (warp & 1) * 32;    // n-half base col

    // ---- stage x via cp.async: 64 rows x 128 k fp32, 8 x 16B per thread
    for (int i = tid; i < RPB * 32; i += 256) {
        int r = i >> 5, q = i & 31;
        int gr = row0 + r;
        unsigned saddr = (unsigned)__cvta_generic_to_shared(&Xs[r][q * 4]);
        if (gr < n_nodes) {
            const float* gp = x + (size_t)gr * D_IN + q * 4;
            asm volatile("cp.async.ca.shared.global [%0], [%1], 16;"
                         :: "r"(saddr), "l"(gp));
        } else {
            asm volatile("st.shared.v4.b32 [%0], {%1,%1,%1,%1};"
                         :: "r"(saddr), "r"(0u));
        }
    }
    asm volatile("cp.async.commit_group;");

    // ---- stage W (overlaps with cp.async in flight): coalesced float4
    //      loads, transposed fp16 stores.  2048 float4 / 256 thr = 8 each.
    for (int i = tid; i < D_IN * 16; i += 256) {
        int r = i >> 4, q = i & 15;     // r = k, q = col-quad
        float4 v = __ldg((const float4*)(w + r * D_OUT + q * 4));
        Wt[q * 4 + 0][r] = __float2half_rn(v.x);
        Wt[q * 4 + 1][r] = __float2half_rn(v.y);
        Wt[q * 4 + 2][r] = __float2half_rn(v.z);
        Wt[q * 4 + 3][r] = __float2half_rn(v.w);
    }

    asm volatile("cp.async.wait_group 0;");
    __syncthreads();

    float acc[4][4];
    #pragma unroll
    for (int nt = 0; nt < 4; nt++)
        #pragma unroll
        for (int c = 0; c < 4; c++) acc[nt][c] = 0.f;

    #pragma unroll
    for (int ks = 0; ks < 8; ks++) {
        int kc = ks * 16;

        // A fragments: read fp32 pairs, convert to half2
        float2 fa0 = *(const float2*)&Xs[wrow + g    ][kc + 2 * tig];
        float2 fa1 = *(const float2*)&Xs[wrow + g + 8][kc + 2 * tig];
        float2 fa2 = *(const float2*)&Xs[wrow + g    ][kc + 2 * tig + 8];
        float2 fa3 = *(const float2*)&Xs[wrow + g + 8][kc + 2 * tig + 8];
        unsigned a0 = f2h2(fa0.x, fa0.y);
        unsigned a1 = f2h2(fa1.x, fa1.y);
        unsigned a2 = f2h2(fa2.x, fa2.y);
        unsigned a3 = f2h2(fa3.x, fa3.y);

        #pragma unroll
        for (int nt = 0; nt < 4; nt++) {
            int col = nhalf + nt * 8 + g;
            unsigned b0 = *(const unsigned*)&Wt[col][kc + 2 * tig];
            unsigned b1 = *(const unsigned*)&Wt[col][kc + 2 * tig + 8];
            asm volatile(
                "mma.sync.aligned.m16n8k16.row.col.f32.f16.f16.f32 "
                "{%0,%1,%2,%3},{%4,%5,%6,%7},{%8,%9},{%0,%1,%2,%3};"
                : "+f"(acc[nt][0]), "+f"(acc[nt][1]),
                  "+f"(acc[nt][2]), "+f"(acc[nt][3])
                : "r"(a0), "r"(a1), "r"(a2), "r"(a3),
                  "r"(b0), "r"(b1));
        }
    }

    // epilogue: (c0,c1)@(row=g, col=2tig), (c2,c3)@(row=g+8)
    int r0 = row0 + wrow + g;
    #pragma unroll
    for (int nt = 0; nt < 4; nt++) {
        int c0 = nhalf + nt * 8 + 2 * tig;
        if (r0 < n_nodes)
            *(__half2*)(g_h + (size_t)r0 * D_OUT + c0) =
                __floats2half2_rn(acc[nt][0], acc[nt][1]);
        if (r0 + 8 < n_nodes)
            *(__half2*)(g_h + (size_t)(r0 + 8) * D_OUT + c0) =
                __floats2half2_rn(acc[nt][2], acc[nt][3]);
    }
}

// ---------------------------------------------------------------------------
// 4-nodes-per-warp aggregation (R14).  Warp = 4 subgroups of 8 lanes; lane
// sl owns cols [8sl, 8sl+7] (one uint4 = 16 B of the fp16 h-row).  One
// LDG.128 instruction gathers 4 edges' lines.  Bias fused.
// ---------------------------------------------------------------------------
__global__ void __launch_bounds__(256)
gather_kernel(const int*   __restrict__ src,
              const float* __restrict__ vals,
              const float* __restrict__ bias,
              float*       __restrict__ out,
              int n_nodes) {
    int warp = (blockIdx.x * 256 + threadIdx.x) >> 5;
    int lane = threadIdx.x & 31;
    int sub  = lane >> 3;      // 0..3 subgroup
    int sl   = lane & 7;       // 0..7 lane-in-subgroup
    int node = warp * 4 + sub;
    if (node >= n_nodes) return;

    int e0 = g_row_ptr[node];
    int e1 = g_row_ptr[node + 1];

    float acc[8];
    #pragma unroll
    for (int c = 0; c < 8; c++) acc[c] = 0.f;

    int e = e0;
    for (; e + 2 <= e1; e += 2) {
        int   s0 = __ldg(src + e);
        int   s1 = __ldg(src + e + 1);
        float v0 = __ldg(vals + e);
        float v1 = __ldg(vals + e + 1);
        uint4 h0 = *(const uint4*)(g_h + ((size_t)s0 << 6) + (sl << 3));
        uint4 h1 = *(const uint4*)(g_h + ((size_t)s1 << 6) + (sl << 3));
        const __half2* p0 = (const __half2*)&h0;
        const __half2* p1 = (const __half2*)&h1;
        #pragma unroll
        for (int q = 0; q < 4; q++) {
            float2 f0 = __half22float2(p0[q]);
            float2 f1 = __half22float2(p1[q]);
            acc[2 * q]     += v0 * f0.x + v1 * f1.x;
            acc[2 * q + 1] += v0 * f0.y + v1 * f1.y;
        }
    }
    if (e < e1) {
        int   s0 = __ldg(src + e);
        float v0 = __ldg(vals + e);
        uint4 h0 = *(const uint4*)(g_h + ((size_t)s0 << 6) + (sl << 3));
        const __half2* p0 = (const __half2*)&h0;
        #pragma unroll
        for (int q = 0; q < 4; q++) {
            float2 f0 = __half22float2(p0[q]);
            acc[2 * q]     += v0 * f0.x;
            acc[2 * q + 1] += v0 * f0.y;
        }
    }

    float4 b0 = __ldg((const float4*)(bias + (sl << 3)));
    float4 b1 = __ldg((const float4*)(bias + (sl << 3) + 4));
    float* o = out + ((size_t)node << 6) + (sl << 3);
    *(float4*)(o)     = make_float4(acc[0] + b0.x, acc[1] + b0.y,
                                    acc[2] + b0.z, acc[3] + b0.w);
    *(float4*)(o + 4) = make_float4(acc[4] + b1.x, acc[5] + b1.y,
                                    acc[6] + b1.z, acc[7] + b1.w);
}

// ---------------------------------------------------------------------------
extern "C" void kernel_launch(void* const* d_in, const int* in_sizes, int n_in,
                              void* d_out, int out_size) {
    const float* x     = (const float*)d_in[0];
    const int*   esrc  = (const int*)  d_in[1];
    const int*   edst  = (const int*)  d_in[2];
    const float* evals = (const float*)d_in[3];
    const float* w     = (const float*)d_in[4];
    const float* bias  = (const float*)d_in[5];
    float*       out   = (float*)d_out;

    int n_nodes = in_sizes[0] / D_IN;
    int n_edges = in_sizes[1];

    gemm_kernel<<<(n_nodes + RPB - 1) / RPB, 256>>>(x, w, n_nodes);

    int nt = (n_edges + 15) / 16;
    rowptr_kernel<<<(nt + 255) / 256, 256>>>(edst, n_edges, n_nodes);

    int warps = (n_nodes + 3) / 4;
    gather_kernel<<<(warps * 32 + 255) / 256, 256>>>(esrc, evals, bias, out, n_nodes);
}

// round 16
// speedup vs baseline: 1.1194x; 1.1194x over previous
#include <cuda_runtime.h>
#include <cuda_fp16.h>

#define D_IN  128
#define D_OUT 64
#define MAX_NODES 50000
#define RPB 64    // rows per block (gemm)

// scratch: h = x @ W stored fp16 (6.4 MB), CSR row pointers
__device__ __half g_h[MAX_NODES * D_OUT];
__device__ int    g_row_ptr[MAX_NODES + 1];

// ---------------------------------------------------------------------------
// CSR row offsets via boundary detection, 16 edges per thread (4x int4, MLP=4).
// ---------------------------------------------------------------------------
__global__ void rowptr_kernel(const int* __restrict__ dst,
                              int n_edges, int n_nodes) {
    int t  = blockIdx.x * blockDim.x + threadIdx.x;
    int e0 = t << 4;
    if (e0 >= n_edges) return;

    int d[17];
    d[0] = (e0 == 0) ? -1 : __ldg(dst + e0 - 1);

    if (e0 + 16 <= n_edges) {
        int4 q0 = __ldg((const int4*)(dst + e0));
        int4 q1 = __ldg((const int4*)(dst + e0 + 4));
        int4 q2 = __ldg((const int4*)(dst + e0 + 8));
        int4 q3 = __ldg((const int4*)(dst + e0 + 12));
        d[1]=q0.x; d[2]=q0.y; d[3]=q0.z; d[4]=q0.w;
        d[5]=q1.x; d[6]=q1.y; d[7]=q1.z; d[8]=q1.w;
        d[9]=q2.x; d[10]=q2.y; d[11]=q2.z; d[12]=q2.w;
        d[13]=q3.x; d[14]=q3.y; d[15]=q3.z; d[16]=q3.w;
    } else {
        #pragma unroll
        for (int j = 0; j < 16; j++)
            d[j + 1] = (e0 + j < n_edges) ? __ldg(dst + e0 + j) : d[j];
    }

    #pragma unroll
    for (int j = 0; j < 16; j++) {
        int ee = e0 + j;
        if (ee < n_edges)
            for (int i = d[j] + 1; i <= d[j + 1]; i++) g_row_ptr[i] = ee;
    }
    if (e0 + 16 >= n_edges) {
        int last = d[16];
        for (int i = last + 1; i <= n_nodes; i++) g_row_ptr[i] = n_edges;
    }
}

// ---------------------------------------------------------------------------
// h = x @ W, mma.m16n8k16 fp16, fp32 accum (R13 structure).
// SINGLE CHANGE vs R13: fragment loads via ldmatrix (LDSM) -- 5 LDSM
// replace 12 scalar LDS per ks per warp.  Stride 136 halves = 68 words:
// row i's 16B segment starts at word 4i mod 32 -> 8 rows hit all 32 banks,
// conflict-free.
// ---------------------------------------------------------------------------
__global__ void __launch_bounds__(256)
gemm_kernel(const float* __restrict__ x,
            const float* __restrict__ w,
            int n_nodes) {
    __shared__ __half Xs[RPB][136];     // 17.4 KB
    __shared__ __half Wt[D_OUT][136];   // 17.4 KB  (W transposed: [n][k])

    int tid   = threadIdx.x;
    int lane  = tid & 31;
    int warp  = tid >> 5;
    int row0  = blockIdx.x * RPB;
    int g     = lane >> 2;          // 0..7
    int tig   = lane & 3;           // 0..3
    int wrow  = (warp >> 1) * 16;   // m-tile base row within block
    int nhalf = (warp & 1) * 32;    // n-half base col
    int lrow  = lane & 7;           // ldmatrix row-in-group
    int seg   = lane >> 3;          // ldmatrix segment 0..3

    // stage x panel: 64 rows x 128 k, fp32 -> fp16  (R13)
    for (int i = tid; i < RPB * 32; i += 256) {
        int r = i >> 5, q = i & 31;
        int gr = row0 + r;
        float4 v = make_float4(0.f, 0.f, 0.f, 0.f);
        if (gr < n_nodes)
            v = __ldg((const float4*)(x + (size_t)gr * D_IN + q * 4));
        __half2* p = (__half2*)&Xs[r][q * 4];
        p[0] = __floats2half2_rn(v.x, v.y);
        p[1] = __floats2half2_rn(v.z, v.w);
    }
    // stage W transposed (R13): thread (col = tid>>2, kq = tid&3), 32 k each
    {
        int col = tid >> 2, kq = tid & 3;
        #pragma unroll
        for (int kk = 0; kk < 32; kk++) {
            int k = kq * 32 + kk;
            Wt[col][k] = __float2half_rn(__ldg(w + k * D_OUT + col));
        }
    }
    __syncthreads();

    float acc[4][4];
    #pragma unroll
    for (int nt = 0; nt < 4; nt++)
        #pragma unroll
        for (int c = 0; c < 4; c++) acc[nt][c] = 0.f;

    #pragma unroll
    for (int ks = 0; ks < 8; ks++) {
        int kc = ks * 16;

        // A fragment via ldmatrix.x4: segments {M00,M10,M01,M11}
        unsigned a0, a1, a2, a3;
        {
            const __half* ap = &Xs[wrow + (seg & 1) * 8 + lrow][kc + (seg >> 1) * 8];
            unsigned sa = (unsigned)__cvta_generic_to_shared(ap);
            asm volatile(
                "ldmatrix.sync.aligned.m8n8.x4.shared.b16 {%0,%1,%2,%3}, [%4];"
                : "=r"(a0), "=r"(a1), "=r"(a2), "=r"(a3) : "r"(sa));
        }

        #pragma unroll
        for (int nt = 0; nt < 4; nt++) {
            int col0 = nhalf + nt * 8;
            // B fragment via ldmatrix.x2: lanes 0-7 -> k-lo, 8-15 -> k-hi
            unsigned b0, b1;
            {
                const __half* bp = &Wt[col0 + lrow][kc + (seg & 1) * 8];
                unsigned sb = (unsigned)__cvta_generic_to_shared(bp);
                asm volatile(
                    "ldmatrix.sync.aligned.m8n8.x2.shared.b16 {%0,%1}, [%2];"
                    : "=r"(b0), "=r"(b1) : "r"(sb));
            }
            asm volatile(
                "mma.sync.aligned.m16n8k16.row.col.f32.f16.f16.f32 "
                "{%0,%1,%2,%3},{%4,%5,%6,%7},{%8,%9},{%0,%1,%2,%3};"
                : "+f"(acc[nt][0]), "+f"(acc[nt][1]),
                  "+f"(acc[nt][2]), "+f"(acc[nt][3])
                : "r"(a0), "r"(a1), "r"(a2), "r"(a3),
                  "r"(b0), "r"(b1));
        }
    }

    // epilogue: (c0,c1)@(row=g, col=2tig), (c2,c3)@(row=g+8)
    int r0 = row0 + wrow + g;
    #pragma unroll
    for (int nt = 0; nt < 4; nt++) {
        int c0 = nhalf + nt * 8 + 2 * tig;
        if (r0 < n_nodes)
            *(__half2*)(g_h + (size_t)r0 * D_OUT + c0) =
                __floats2half2_rn(acc[nt][0], acc[nt][1]);
        if (r0 + 8 < n_nodes)
            *(__half2*)(g_h + (size_t)(r0 + 8) * D_OUT + c0) =
                __floats2half2_rn(acc[nt][2], acc[nt][3]);
    }
}

// ---------------------------------------------------------------------------
// 4-nodes-per-warp aggregation (R14, proven).  Warp = 4 subgroups of 8
// lanes; lane sl owns cols [8sl, 8sl+7] (one uint4 = 16 B of the fp16
// h-row).  One LDG.128 instruction gathers 4 edges' lines.  Bias fused.
// ---------------------------------------------------------------------------
__global__ void __launch_bounds__(256)
gather_kernel(const int*   __restrict__ src,
              const float* __restrict__ vals,
              const float* __restrict__ bias,
              float*       __restrict__ out,
              int n_nodes) {
    int warp = (blockIdx.x * 256 + threadIdx.x) >> 5;
    int lane = threadIdx.x & 31;
    int sub  = lane >> 3;      // 0..3 subgroup
    int sl   = lane & 7;       // 0..7 lane-in-subgroup
    int node = warp * 4 + sub;
    if (node >= n_nodes) return;

    int e0 = g_row_ptr[node];
    int e1 = g_row_ptr[node + 1];

    float acc[8];
    #pragma unroll
    for (int c = 0; c < 8; c++) acc[c] = 0.f;

    int e = e0;
    for (; e + 2 <= e1; e += 2) {
        int   s0 = __ldg(src + e);
        int   s1 = __ldg(src + e + 1);
        float v0 = __ldg(vals + e);
        float v1 = __ldg(vals + e + 1);
        uint4 h0 = *(const uint4*)(g_h + ((size_t)s0 << 6) + (sl << 3));
        uint4 h1 = *(const uint4*)(g_h + ((size_t)s1 << 6) + (sl << 3));
        const __half2* p0 = (const __half2*)&h0;
        const __half2* p1 = (const __half2*)&h1;
        #pragma unroll
        for (int q = 0; q < 4; q++) {
            float2 f0 = __half22float2(p0[q]);
            float2 f1 = __half22float2(p1[q]);
            acc[2 * q]     += v0 * f0.x + v1 * f1.x;
            acc[2 * q + 1] += v0 * f0.y + v1 * f1.y;
        }
    }
    if (e < e1) {
        int   s0 = __ldg(src + e);
        float v0 = __ldg(vals + e);
        uint4 h0 = *(const uint4*)(g_h + ((size_t)s0 << 6) + (sl << 3));
        const __half2* p0 = (const __half2*)&h0;
        #pragma unroll
        for (int q = 0; q < 4; q++) {
            float2 f0 = __half22float2(p0[q]);
            acc[2 * q]     += v0 * f0.x;
            acc[2 * q + 1] += v0 * f0.y;
        }
    }

    float4 b0 = __ldg((const float4*)(bias + (sl << 3)));
    float4 b1 = __ldg((const float4*)(bias + (sl << 3) + 4));
    float* o = out + ((size_t)node << 6) + (sl << 3);
    *(float4*)(o)     = make_float4(acc[0] + b0.x, acc[1] + b0.y,
                                    acc[2] + b0.z, acc[3] + b0.w);
    *(float4*)(o + 4) = make_float4(acc[4] + b1.x, acc[5] + b1.y,
                                    acc[6] + b1.z, acc[7] + b1.w);
}

// ---------------------------------------------------------------------------
extern "C" void kernel_launch(void* const* d_in, const int* in_sizes, int n_in,
                              void* d_out, int out_size) {
    const float* x     = (const float*)d_in[0];
    const int*   esrc  = (const int*)  d_in[1];
    const int*   edst  = (const int*)  d_in[2];
    const float* evals = (const float*)d_in[3];
    const float* w     = (const float*)d_in[4];
    const float* bias  = (const float*)d_in[5];
    float*       out   = (float*)d_out;

    int n_nodes = in_sizes[0] / D_IN;
    int n_edges = in_sizes[1];

    gemm_kernel<<<(n_nodes + RPB - 1) / RPB, 256>>>(x, w, n_nodes);

    int nt = (n_edges + 15) / 16;
    rowptr_kernel<<<(nt + 255) / 256, 256>>>(edst, n_edges, n_nodes);

    int warps = (n_nodes + 3) / 4;
    gather_kernel<<<(warps * 32 + 255) / 256, 256>>>(esrc, evals, bias, out, n_nodes);
}